// round 3
// baseline (speedup 1.0000x reference)
#include <cuda_runtime.h>
#include <mma.h>
#include <cfloat>
#include <math.h>

using namespace nvcuda;

#define N_TOK 8192
#define KDIM  4096
#define VDIM  32000
#define VSPLIT 10
#define VPS   (VDIM / VSPLIT)   // 3200 columns per split
#define MT 128
#define NT 64
#define KT 16                   // K-slab width (floats)
#define NTILES (VPS / NT)       // 50
#define KCH (KDIM / KT)         // 256
#define LDAF 20                 // KT + 4 pad (floats); 80B rows, 16B-aligned
#define LDC 68                  // NT + 4 pad (floats)
#define MBLK (N_TOK / MT)       // 64
#define STAGE_F ((MT + NT) * LDAF)   // floats per pipeline stage

// -------- device scratch (allocation-free rule: __device__ globals) --------
__device__ float g_pmax[VSPLIT * N_TOK];
__device__ float g_psum[VSPLIT * N_TOK];
__device__ float g_tlog[N_TOK];
__device__ float g_bnll[MBLK];
__device__ int   g_bcnt[MBLK];

// -------- fused tf32 GEMM + online logsumexp + target gather --------
// grid: (MBLK, VSPLIT), block: 256 threads (8 warps, 4x2 warp grid, warp tile 32x32)
__global__ void __launch_bounds__(256, 2)
lmhead_ce_kernel(const float* __restrict__ input,
                 const float* __restrict__ weight,
                 const int* __restrict__ target) {
    // smem overlay: [2][A 128xLDAF | B 64xLDAF] floats (30720 B)  OR  C [128][LDC] floats (34816 B)
    __shared__ __align__(16) unsigned char smem_raw[MT * LDC * 4];
    float* Sm = reinterpret_cast<float*>(smem_raw);
    float* Cs = reinterpret_cast<float*>(smem_raw);

    const int tid = threadIdx.x;
    const int m0 = blockIdx.x * MT;
    const int vs = blockIdx.y;
    const int vbase = vs * VPS;
    const int warp = tid >> 5;
    const int wm = warp & 3;   // 0..3 -> rows wm*32
    const int wn = warp >> 2;  // 0..1 -> cols wn*32

    // gmem->smem decomposition: float4 chunks; K-slab = 16 floats = 4 chunks/row
    const int rowA0 = tid >> 2;        // 0..63
    const int chk   = tid & 3;         // chunk within slab
    const size_t offA0 = (size_t)(m0 + rowA0) * KDIM + chk * 4;
    const size_t offA1 = (size_t)(m0 + rowA0 + 64) * KDIM + chk * 4;
    const int sA0 = rowA0 * LDAF + chk * 4;
    const int sA1 = (rowA0 + 64) * LDAF + chk * 4;
    const int sB  = MT * LDAF + rowA0 * LDAF + chk * 4;   // rowB == rowA0 (0..63)

    float rmax = -FLT_MAX, rsum = 0.f;
    const int tgt = (tid < MT) ? target[m0 + tid] : -1;   // int32! (JAX x64 disabled)

    wmma::fragment<wmma::matrix_a, 16,16,8, wmma::precision::tf32, wmma::row_major> fa[2];
    wmma::fragment<wmma::matrix_b, 16,16,8, wmma::precision::tf32, wmma::col_major> fb[2];
    wmma::fragment<wmma::accumulator, 16,16,8, float> fc[2][2];

    for (int nt = 0; nt < NTILES; nt++) {
        const int vcol0 = vbase + nt * NT;
        const size_t offB = (size_t)(vcol0 + rowA0) * KDIM + chk * 4;

        #pragma unroll
        for (int i = 0; i < 2; i++)
            #pragma unroll
            for (int j = 0; j < 2; j++)
                wmma::fill_fragment(fc[i][j], 0.f);

        // prologue: stage 0
        float4 ra0 = *reinterpret_cast<const float4*>(input  + offA0);
        float4 ra1 = *reinterpret_cast<const float4*>(input  + offA1);
        float4 rb  = *reinterpret_cast<const float4*>(weight + offB);
        *reinterpret_cast<float4*>(&Sm[sA0]) = ra0;
        *reinterpret_cast<float4*>(&Sm[sA1]) = ra1;
        *reinterpret_cast<float4*>(&Sm[sB])  = rb;
        __syncthreads();

        int buf = 0;
        #pragma unroll 1
        for (int kc = 0; kc < KCH; kc++) {
            if (kc + 1 < KCH) {     // prefetch next slab into registers
                const int k0 = (kc + 1) * KT;
                ra0 = *reinterpret_cast<const float4*>(input  + offA0 + k0);
                ra1 = *reinterpret_cast<const float4*>(input  + offA1 + k0);
                rb  = *reinterpret_cast<const float4*>(weight + offB  + k0);
            }
            const float* Ab = Sm + buf * STAGE_F;
            const float* Bb = Ab + MT * LDAF;
            #pragma unroll
            for (int ks = 0; ks < 2; ks++) {
                wmma::load_matrix_sync(fa[0], Ab + (wm*32 +  0) * LDAF + ks*8, LDAF);
                wmma::load_matrix_sync(fa[1], Ab + (wm*32 + 16) * LDAF + ks*8, LDAF);
                wmma::load_matrix_sync(fb[0], Bb + (wn*32 +  0) * LDAF + ks*8, LDAF);
                wmma::load_matrix_sync(fb[1], Bb + (wn*32 + 16) * LDAF + ks*8, LDAF);
                #pragma unroll
                for (int e = 0; e < fa[0].num_elements; e++) {
                    fa[0].x[e] = wmma::__float_to_tf32(fa[0].x[e]);
                    fa[1].x[e] = wmma::__float_to_tf32(fa[1].x[e]);
                }
                #pragma unroll
                for (int e = 0; e < fb[0].num_elements; e++) {
                    fb[0].x[e] = wmma::__float_to_tf32(fb[0].x[e]);
                    fb[1].x[e] = wmma::__float_to_tf32(fb[1].x[e]);
                }
                #pragma unroll
                for (int i = 0; i < 2; i++)
                    #pragma unroll
                    for (int j = 0; j < 2; j++)
                        wmma::mma_sync(fc[i][j], fa[i], fb[j], fc[i][j]);
            }
            if (kc + 1 < KCH) {     // fill the other stage (nobody reads it now)
                float* St = Sm + (buf ^ 1) * STAGE_F;
                *reinterpret_cast<float4*>(&St[sA0]) = ra0;
                *reinterpret_cast<float4*>(&St[sA1]) = ra1;
                *reinterpret_cast<float4*>(&St[sB])  = rb;
            }
            __syncthreads();
            buf ^= 1;
        }

        // epilogue: logits tile -> smem (overlays A/B; mainloop's final sync guards it)
        #pragma unroll
        for (int i = 0; i < 2; i++)
            #pragma unroll
            for (int j = 0; j < 2; j++)
                wmma::store_matrix_sync(&Cs[(wm*32 + i*16) * LDC + wn*32 + j*16],
                                        fc[i][j], LDC, wmma::mem_row_major);
        __syncthreads();

        if (tid < MT) {  // one thread owns one row; running state stays in registers
            const float* crow = &Cs[tid * LDC];
            float tmax = -FLT_MAX;
            #pragma unroll 8
            for (int j = 0; j < NT; j++) tmax = fmaxf(tmax, crow[j]);
            float nm = fmaxf(rmax, tmax);
            float acc = 0.f;
            #pragma unroll 8
            for (int j = 0; j < NT; j++) acc += __expf(crow[j] - nm);
            rsum = rsum * __expf(rmax - nm) + acc;
            rmax = nm;
            int dt = tgt - vcol0;
            if (dt >= 0 && dt < NT) g_tlog[m0 + tid] = crow[dt];
        }
        __syncthreads();   // protect Cs before next tile's prologue STS
    }

    if (tid < MT) {
        g_pmax[vs * N_TOK + m0 + tid] = rmax;
        g_psum[vs * N_TOK + m0 + tid] = rsum;
    }
}

// -------- combine splits per row, block-sum NLL --------
__global__ void reduce1_kernel(const int* __restrict__ target) {
    const int r = blockIdx.x * 128 + threadIdx.x;
    float M = -FLT_MAX;
    #pragma unroll
    for (int s = 0; s < VSPLIT; s++) M = fmaxf(M, g_pmax[s * N_TOK + r]);
    float S = 0.f;
    #pragma unroll
    for (int s = 0; s < VSPLIT; s++) S += g_psum[s * N_TOK + r] * __expf(g_pmax[s * N_TOK + r] - M);
    int t = target[r];
    int valid = (t != -100);
    float nll = valid ? (M + logf(S) - g_tlog[r]) : 0.f;

    __shared__ float sh[128];
    __shared__ int   sc[128];
    sh[threadIdx.x] = nll; sc[threadIdx.x] = valid;
    __syncthreads();
    for (int o = 64; o > 0; o >>= 1) {
        if (threadIdx.x < o) { sh[threadIdx.x] += sh[threadIdx.x + o]; sc[threadIdx.x] += sc[threadIdx.x + o]; }
        __syncthreads();
    }
    if (threadIdx.x == 0) { g_bnll[blockIdx.x] = sh[0]; g_bcnt[blockIdx.x] = sc[0]; }
}

// -------- final deterministic reduction --------
__global__ void reduce2_kernel(float* __restrict__ out) {
    __shared__ float sh[64];
    __shared__ int   sc[64];
    int t = threadIdx.x;
    sh[t] = g_bnll[t]; sc[t] = g_bcnt[t];
    __syncthreads();
    for (int o = 32; o > 0; o >>= 1) {
        if (t < o) { sh[t] += sh[t + o]; sc[t] += sc[t + o]; }
        __syncthreads();
    }
    if (t == 0) {
        int c = sc[0] > 0 ? sc[0] : 1;
        out[0] = sh[0] / (float)c;
    }
}

extern "C" void kernel_launch(void* const* d_in, const int* in_sizes, int n_in,
                              void* d_out, int out_size) {
    const float* input  = (const float*)d_in[0];   // [8192, 4096] f32
    const float* weight = (const float*)d_in[1];   // [32000, 4096] f32
    const int* target   = (const int*)d_in[2];     // [8192] int32 (JAX x64 off)
    float* out = (float*)d_out;                    // scalar f32

    dim3 grid(MBLK, VSPLIT);
    lmhead_ce_kernel<<<grid, 256>>>(input, weight, target);

    reduce1_kernel<<<MBLK, 128>>>(target);
    reduce2_kernel<<<1, 64>>>(out);
}

// round 5
// speedup vs baseline: 4.0223x; 4.0223x over previous
#include <cuda_runtime.h>
#include <cuda_bf16.h>
#include <cfloat>
#include <math.h>
#include <stdint.h>

#define N_TOK 8192
#define KDIM  4096
#define VDIM  32000
#define MT    128
#define NTILE 128
#define KS    32                   // K elems per stage
#define NST   4                    // cp.async stages
#define KSTG  (KDIM / KS)          // 128
#define NVT   (VDIM / NTILE)       // 250
#define VSPLIT 2
#define TPS   (NVT / VSPLIT)       // 125 tiles per split
#define MBLK  (N_TOK / MT)         // 64
#define ROWB  80                   // padded smem row: 40 bf16 = 80B (conflict-free ldmatrix)
#define A_BYTES (MT * ROWB)        // 10240
#define STAGE_BYTES (A_BYTES + NTILE * ROWB)   // 20480
#define SMEM_DYN (NST * STAGE_BYTES)           // 81920

// -------- device scratch --------
__device__ __nv_bfloat16 g_in_bf[(size_t)N_TOK * KDIM];
__device__ __nv_bfloat16 g_w_bf[(size_t)VDIM * KDIM];
__device__ float g_pmax[VSPLIT * N_TOK];
__device__ float g_psum[VSPLIT * N_TOK];
__device__ float g_tlog[N_TOK];
__device__ float g_bnll[MBLK];
__device__ int   g_bcnt[MBLK];

// -------- helpers --------
__device__ __forceinline__ uint32_t smem_u32(const void* p) {
    uint32_t a;
    asm("{ .reg .u64 t; cvta.to.shared.u64 t, %1; cvt.u32.u64 %0, t; }" : "=r"(a) : "l"(p));
    return a;
}
__device__ __forceinline__ void cp_async16(uint32_t sa, const void* g) {
    asm volatile("cp.async.cg.shared.global [%0], [%1], 16;" :: "r"(sa), "l"(g));
}
#define CP_COMMIT() asm volatile("cp.async.commit_group;" ::: "memory")
#define CP_WAIT(n)  asm volatile("cp.async.wait_group %0;" :: "n"(n) : "memory")

#define LDSM4(d0,d1,d2,d3,addr) \
    asm volatile("ldmatrix.sync.aligned.m8n8.x4.shared.b16 {%0,%1,%2,%3}, [%4];" \
        : "=r"(d0),"=r"(d1),"=r"(d2),"=r"(d3) : "r"(addr))

#define MMA16816(d,a0,a1,a2,a3,b0,b1) \
    asm volatile("mma.sync.aligned.m16n8k16.row.col.f32.bf16.bf16.f32 " \
        "{%0,%1,%2,%3},{%4,%5,%6,%7},{%8,%9},{%0,%1,%2,%3};" \
        : "+f"((d)[0]),"+f"((d)[1]),"+f"((d)[2]),"+f"((d)[3]) \
        : "r"(a0),"r"(a1),"r"(a2),"r"(a3),"r"(b0),"r"(b1))

// -------- fp32 -> bf16 conversion --------
__global__ void cvt_kernel(const float* __restrict__ src, size_t n4, int which) {
    __nv_bfloat16* dst = which ? g_w_bf : g_in_bf;
    uint2* d2 = reinterpret_cast<uint2*>(dst);
    const float4* s4 = reinterpret_cast<const float4*>(src);
    size_t i = (size_t)blockIdx.x * blockDim.x + threadIdx.x;
    size_t stride = (size_t)gridDim.x * blockDim.x;
    for (; i < n4; i += stride) {
        float4 v = s4[i];
        __nv_bfloat162 lo = __floats2bfloat162_rn(v.x, v.y);
        __nv_bfloat162 hi = __floats2bfloat162_rn(v.z, v.w);
        uint2 o;
        o.x = *reinterpret_cast<unsigned int*>(&lo);
        o.y = *reinterpret_cast<unsigned int*>(&hi);
        d2[i] = o;
    }
}

// -------- bf16 mma.sync GEMM + register-resident online logsumexp --------
// grid (64, 2), block 256 = 8 warps, warp grid 4(m) x 2(n), warp tile 32x64
__global__ void __launch_bounds__(256, 1)
lmhead_mma(const int* __restrict__ target) {
    extern __shared__ __align__(128) unsigned char dsm[];
    __shared__ float smax[2][MT], ssum[2][MT], stl[2][MT];

    const int tid = threadIdx.x, lane = tid & 31, warp = tid >> 5;
    const int wm = warp & 3, wn = warp >> 2;
    const int m0 = blockIdx.x * MT;
    const int vs = blockIdx.y, vstart = vs * TPS;
    const uint32_t sbase = smem_u32(dsm);

    // producer mapping: thread covers 32B (2 chunks) of one row for A and B
    const int pr = tid >> 1;            // row 0..127
    const int pc = (tid & 1) * 16;      // element offset (0 or 16)
    const __nv_bfloat16* gA = g_in_bf + (size_t)(m0 + pr) * KDIM + pc;
    const uint32_t sAoff = (uint32_t)pr * ROWB + pc * 2;
    const uint32_t sBoff = A_BYTES + (uint32_t)pr * ROWB + pc * 2;

    // ldmatrix base offsets
    const int l15 = lane & 15, lh = lane >> 4, lq = lane & 3, rq = lane >> 2;
    const uint32_t aBase = (uint32_t)(wm * 32 + l15) * ROWB + lh * 16;
    const uint32_t bBase = A_BYTES + (uint32_t)(wn * 64 + l15) * ROWB + lh * 16;

    // per-lane running logsumexp state for its 4 rows
    float rmax[4], rsum[4], tlog[4];
    int tgtr[4];
    #pragma unroll
    for (int i = 0; i < 4; i++) { rmax[i] = -FLT_MAX; rsum[i] = 0.f; tlog[i] = 0.f; }
    #pragma unroll
    for (int mi = 0; mi < 2; mi++)
        #pragma unroll
        for (int h = 0; h < 2; h++)
            tgtr[mi * 2 + h] = target[m0 + wm * 32 + mi * 16 + h * 8 + rq];

    for (int lt = 0; lt < TPS; ++lt) {
        const int vt = vstart + lt;
        const int vcol0 = vt * NTILE;
        const __nv_bfloat16* gB = g_w_bf + (size_t)(vcol0 + pr) * KDIM + pc;

        float acc[2][8][4];
        #pragma unroll
        for (int mi = 0; mi < 2; mi++)
            #pragma unroll
            for (int nj = 0; nj < 8; nj++)
                #pragma unroll
                for (int q = 0; q < 4; q++) acc[mi][nj][q] = 0.f;

        // prologue: stages 0..NST-2
        #pragma unroll
        for (int s = 0; s < NST - 1; s++) {
            const uint32_t st = sbase + s * STAGE_BYTES;
            const int k0 = s * KS;
            cp_async16(st + sAoff,      gA + k0);
            cp_async16(st + sAoff + 16, gA + k0 + 8);
            cp_async16(st + sBoff,      gB + k0);
            cp_async16(st + sBoff + 16, gB + k0 + 8);
            CP_COMMIT();
        }

        #pragma unroll 1
        for (int ks = 0; ks < KSTG; ++ks) {
            CP_WAIT(NST - 2);
            __syncthreads();
            const uint32_t st = sbase + (ks & (NST - 1)) * STAGE_BYTES;
            #pragma unroll
            for (int k2 = 0; k2 < 2; k2++) {
                uint32_t A0[4], A1[4], B[4][4];
                LDSM4(A0[0], A0[1], A0[2], A0[3], st + aBase + k2 * 32);
                LDSM4(A1[0], A1[1], A1[2], A1[3], st + aBase + 16 * ROWB + k2 * 32);
                #pragma unroll
                for (int g = 0; g < 4; g++)
                    LDSM4(B[g][0], B[g][1], B[g][2], B[g][3],
                          st + bBase + g * 16 * ROWB + k2 * 32);
                #pragma unroll
                for (int g = 0; g < 4; g++) {
                    MMA16816(acc[0][2*g],   A0[0],A0[1],A0[2],A0[3], B[g][0], B[g][2]);
                    MMA16816(acc[0][2*g+1], A0[0],A0[1],A0[2],A0[3], B[g][1], B[g][3]);
                    MMA16816(acc[1][2*g],   A1[0],A1[1],A1[2],A1[3], B[g][0], B[g][2]);
                    MMA16816(acc[1][2*g+1], A1[0],A1[1],A1[2],A1[3], B[g][1], B[g][3]);
                }
            }
            if (ks + NST - 1 < KSTG) {      // prefetch
                const uint32_t st2 = sbase + ((ks + NST - 1) & (NST - 1)) * STAGE_BYTES;
                const int k0 = (ks + NST - 1) * KS;
                cp_async16(st2 + sAoff,      gA + k0);
                cp_async16(st2 + sAoff + 16, gA + k0 + 8);
                cp_async16(st2 + sBoff,      gB + k0);
                cp_async16(st2 + sBoff + 16, gB + k0 + 8);
            }
            CP_COMMIT();
        }

        // register-resident epilogue: online logsumexp over this tile's 16 cols/lane
        #pragma unroll
        for (int mi = 0; mi < 2; mi++)
            #pragma unroll
            for (int h = 0; h < 2; h++) {
                const int ri = mi * 2 + h;
                float vmax = -FLT_MAX;
                #pragma unroll
                for (int nj = 0; nj < 8; nj++) {
                    vmax = fmaxf(vmax, acc[mi][nj][h * 2]);
                    vmax = fmaxf(vmax, acc[mi][nj][h * 2 + 1]);
                }
                const float nm = fmaxf(rmax[ri], vmax);
                float s = 0.f;
                #pragma unroll
                for (int nj = 0; nj < 8; nj++) {
                    s += __expf(acc[mi][nj][h * 2]     - nm);
                    s += __expf(acc[mi][nj][h * 2 + 1] - nm);
                }
                rsum[ri] = rsum[ri] * __expf(rmax[ri] - nm) + s;
                rmax[ri] = nm;
                const int dt = tgtr[ri] - vcol0;
                if (dt >= 0 && dt < NTILE) {
                    #pragma unroll
                    for (int nj = 0; nj < 8; nj++) {
                        const int c0 = wn * 64 + (nj >> 1) * 16 + (nj & 1) * 8 + lq * 2;
                        if (dt == c0)     tlog[ri] = acc[mi][nj][h * 2];
                        if (dt == c0 + 1) tlog[ri] = acc[mi][nj][h * 2 + 1];
                    }
                }
            }
    }

    // merge the 4 lanes per lane-group (same rows): xor 1, 2
    #pragma unroll
    for (int ri = 0; ri < 4; ri++) {
        #pragma unroll
        for (int off = 1; off < 4; off <<= 1) {
            const float om = __shfl_xor_sync(0xFFFFFFFFu, rmax[ri], off);
            const float os = __shfl_xor_sync(0xFFFFFFFFu, rsum[ri], off);
            const float nm = fmaxf(rmax[ri], om);
            rsum[ri] = rsum[ri] * __expf(rmax[ri] - nm) + os * __expf(om - nm);
            rmax[ri] = nm;
            tlog[ri] += __shfl_xor_sync(0xFFFFFFFFu, tlog[ri], off);
        }
    }
    // cross-warp (wn halves) via smem
    if (lq == 0) {
        #pragma unroll
        for (int ri = 0; ri < 4; ri++) {
            const int row = wm * 32 + (ri >> 1) * 16 + (ri & 1) * 8 + rq;
            smax[wn][row] = rmax[ri];
            ssum[wn][row] = rsum[ri];
            stl[wn][row]  = tlog[ri];
        }
    }
    __syncthreads();
    if (tid < MT) {
        const float m0v = smax[0][tid], m1v = smax[1][tid];
        const float M = fmaxf(m0v, m1v);
        const float S = ssum[0][tid] * __expf(m0v - M) + ssum[1][tid] * __expf(m1v - M);
        g_pmax[vs * N_TOK + m0 + tid] = M;
        g_psum[vs * N_TOK + m0 + tid] = S;
        const int t = target[m0 + tid];
        if (t >= vstart * NTILE && t < (vstart + TPS) * NTILE)
            g_tlog[m0 + tid] = stl[0][tid] + stl[1][tid];
    }
}

// -------- combine splits per row, block-sum NLL --------
__global__ void reduce1_kernel(const int* __restrict__ target) {
    const int r = blockIdx.x * 128 + threadIdx.x;
    float M = -FLT_MAX;
    #pragma unroll
    for (int s = 0; s < VSPLIT; s++) M = fmaxf(M, g_pmax[s * N_TOK + r]);
    float S = 0.f;
    #pragma unroll
    for (int s = 0; s < VSPLIT; s++) S += g_psum[s * N_TOK + r] * __expf(g_pmax[s * N_TOK + r] - M);
    int t = target[r];
    int valid = (t != -100);
    float nll = valid ? (M + logf(S) - g_tlog[r]) : 0.f;

    __shared__ float sh[128];
    __shared__ int   sc[128];
    sh[threadIdx.x] = nll; sc[threadIdx.x] = valid;
    __syncthreads();
    for (int o = 64; o > 0; o >>= 1) {
        if (threadIdx.x < o) { sh[threadIdx.x] += sh[threadIdx.x + o]; sc[threadIdx.x] += sc[threadIdx.x + o]; }
        __syncthreads();
    }
    if (threadIdx.x == 0) { g_bnll[blockIdx.x] = sh[0]; g_bcnt[blockIdx.x] = sc[0]; }
}

__global__ void reduce2_kernel(float* __restrict__ out) {
    __shared__ float sh[64];
    __shared__ int   sc[64];
    int t = threadIdx.x;
    sh[t] = g_bnll[t]; sc[t] = g_bcnt[t];
    __syncthreads();
    for (int o = 32; o > 0; o >>= 1) {
        if (t < o) { sh[t] += sh[t + o]; sc[t] += sc[t + o]; }
        __syncthreads();
    }
    if (t == 0) {
        int c = sc[0] > 0 ? sc[0] : 1;
        out[0] = sh[0] / (float)c;
    }
}

extern "C" void kernel_launch(void* const* d_in, const int* in_sizes, int n_in,
                              void* d_out, int out_size) {
    const float* input  = (const float*)d_in[0];   // [8192,4096] f32
    const float* weight = (const float*)d_in[1];   // [32000,4096] f32
    const int* target   = (const int*)d_in[2];     // [8192] int32
    float* out = (float*)d_out;

    cudaFuncSetAttribute(lmhead_mma, cudaFuncAttributeMaxDynamicSharedMemorySize, SMEM_DYN);

    cvt_kernel<<<4096, 256>>>(input,  (size_t)N_TOK * KDIM / 4, 0);
    cvt_kernel<<<8192, 256>>>(weight, (size_t)VDIM * KDIM / 4, 1);

    dim3 grid(MBLK, VSPLIT);
    lmhead_mma<<<grid, 256, SMEM_DYN>>>(target);

    reduce1_kernel<<<MBLK, 128>>>(target);
    reduce2_kernel<<<1, 64>>>(out);
}

// round 6
// speedup vs baseline: 5.2499x; 1.3052x over previous
#include <cuda_runtime.h>
#include <cuda_bf16.h>
#include <cfloat>
#include <math.h>
#include <stdint.h>

#define N_TOK 8192
#define KDIM  4096
#define VDIM  32000
#define MT    128
#define NTILE 256
#define KS    32                   // K elems per stage
#define NST   4                    // cp.async stages
#define KSTG  (KDIM / KS)          // 128
#define NVT   (VDIM / NTILE)       // 125
#define VSPLIT 2
#define VS0   63                   // tiles in split 0 (split 1: 62)
#define MBLK  (N_TOK / MT)         // 64
#define ROWB  80                   // padded smem row: 32 K-elems + 8 pad (80B)
#define A_BYTES (MT * ROWB)        // 10240
#define STAGE_BYTES ((MT + NTILE) * ROWB)      // 30720
#define SMEM_DYN (NST * STAGE_BYTES)           // 122880

// -------- device scratch --------
__device__ __nv_bfloat16 g_in_bf[(size_t)N_TOK * KDIM];
__device__ __nv_bfloat16 g_w_bf[(size_t)VDIM * KDIM];
__device__ float g_pmax[VSPLIT * N_TOK];
__device__ float g_psum[VSPLIT * N_TOK];
__device__ float g_tlog[N_TOK];
__device__ float g_bnll[MBLK];
__device__ int   g_bcnt[MBLK];

// -------- helpers --------
__device__ __forceinline__ uint32_t smem_u32(const void* p) {
    uint32_t a;
    asm("{ .reg .u64 t; cvta.to.shared.u64 t, %1; cvt.u32.u64 %0, t; }" : "=r"(a) : "l"(p));
    return a;
}
__device__ __forceinline__ void cp_async16(uint32_t sa, const void* g) {
    asm volatile("cp.async.cg.shared.global [%0], [%1], 16;" :: "r"(sa), "l"(g));
}
#define CP_COMMIT() asm volatile("cp.async.commit_group;" ::: "memory")
#define CP_WAIT(n)  asm volatile("cp.async.wait_group %0;" :: "n"(n) : "memory")

#define LDSM4(d0,d1,d2,d3,addr) \
    asm volatile("ldmatrix.sync.aligned.m8n8.x4.shared.b16 {%0,%1,%2,%3}, [%4];" \
        : "=r"(d0),"=r"(d1),"=r"(d2),"=r"(d3) : "r"(addr))

#define MMA16816(d,a0,a1,a2,a3,b0,b1) \
    asm volatile("mma.sync.aligned.m16n8k16.row.col.f32.bf16.bf16.f32 " \
        "{%0,%1,%2,%3},{%4,%5,%6,%7},{%8,%9},{%0,%1,%2,%3};" \
        : "+f"((d)[0]),"+f"((d)[1]),"+f"((d)[2]),"+f"((d)[3]) \
        : "r"(a0),"r"(a1),"r"(a2),"r"(a3),"r"(b0),"r"(b1))

// -------- fp32 -> bf16 conversion --------
__global__ void cvt_kernel(const float* __restrict__ src, size_t n4, int which) {
    __nv_bfloat16* dst = which ? g_w_bf : g_in_bf;
    uint2* d2 = reinterpret_cast<uint2*>(dst);
    const float4* s4 = reinterpret_cast<const float4*>(src);
    size_t i = (size_t)blockIdx.x * blockDim.x + threadIdx.x;
    size_t stride = (size_t)gridDim.x * blockDim.x;
    for (; i < n4; i += stride) {
        float4 v = s4[i];
        __nv_bfloat162 lo = __floats2bfloat162_rn(v.x, v.y);
        __nv_bfloat162 hi = __floats2bfloat162_rn(v.z, v.w);
        uint2 o;
        o.x = *reinterpret_cast<unsigned int*>(&lo);
        o.y = *reinterpret_cast<unsigned int*>(&hi);
        d2[i] = o;
    }
}

// -------- bf16 mma.sync GEMM + register-resident online logsumexp --------
// grid (64, 2), block 256 = 8 warps, warp grid 2(m) x 4(n), warp tile 64x64
__global__ void __launch_bounds__(256)
lmhead_mma(const int* __restrict__ target) {
    extern __shared__ __align__(128) unsigned char dsm[];
    __shared__ float smax[4][MT], ssum[4][MT], stl[4][MT];

    const int tid = threadIdx.x, lane = tid & 31, warp = tid >> 5;
    const int wm = warp & 1, wn = warp >> 1;   // wm 0..1, wn 0..3
    const int m0 = blockIdx.x * MT;
    const int vs = blockIdx.y;
    const int vstart = vs ? VS0 : 0;
    const int ntiles = vs ? (NVT - VS0) : VS0;
    const uint32_t sbase = smem_u32(dsm);

    // producer mapping: 384 rows x 4 chunks(16B) = 1536 ids; 6 per thread
    int prow[6], pchk[6];
    #pragma unroll
    for (int j = 0; j < 6; j++) { const int id = tid + j * 256; prow[j] = id >> 2; pchk[j] = id & 3; }

    // ldmatrix base offsets
    const int l15 = lane & 15, lh = lane >> 4, lq = lane & 3, rq = lane >> 2;
    const uint32_t aBase = (uint32_t)(wm * 64 + l15) * ROWB + lh * 16;
    const uint32_t bBase = A_BYTES + (uint32_t)(wn * 64 + l15) * ROWB + lh * 16;

    // per-lane running logsumexp state: 8 rows/lane (4 m-frags x 2 halves)
    float rmax[8], rsum[8], tlog[8];
    int tgtr[8];
    #pragma unroll
    for (int i = 0; i < 8; i++) { rmax[i] = -FLT_MAX; rsum[i] = 0.f; tlog[i] = 0.f; }
    #pragma unroll
    for (int mi = 0; mi < 4; mi++)
        #pragma unroll
        for (int h = 0; h < 2; h++)
            tgtr[mi * 2 + h] = target[m0 + wm * 64 + mi * 16 + h * 8 + rq];

    for (int lt = 0; lt < ntiles; ++lt) {
        const int vcol0 = (vstart + lt) * NTILE;

        float acc[4][8][4];
        #pragma unroll
        for (int mi = 0; mi < 4; mi++)
            #pragma unroll
            for (int nj = 0; nj < 8; nj++)
                #pragma unroll
                for (int q = 0; q < 4; q++) acc[mi][nj][q] = 0.f;

        // prologue: stages 0..NST-2
        #pragma unroll
        for (int s = 0; s < NST - 1; s++) {
            const uint32_t st = sbase + s * STAGE_BYTES;
            const int k0 = s * KS;
            #pragma unroll
            for (int j = 0; j < 6; j++) {
                const int row = prow[j], ch = pchk[j];
                const __nv_bfloat16* g = (row < MT)
                    ? g_in_bf + (size_t)(m0 + row) * KDIM + k0 + ch * 8
                    : g_w_bf + (size_t)(vcol0 + row - MT) * KDIM + k0 + ch * 8;
                cp_async16(st + (uint32_t)row * ROWB + ch * 16, g);
            }
            CP_COMMIT();
        }

        #pragma unroll 1
        for (int ks = 0; ks < KSTG; ++ks) {
            CP_WAIT(NST - 2);
            __syncthreads();
            const uint32_t st = sbase + (ks & (NST - 1)) * STAGE_BYTES;
            #pragma unroll
            for (int k2 = 0; k2 < 2; k2++) {
                uint32_t Af[4][4], Bf[4][4];
                #pragma unroll
                for (int mi = 0; mi < 4; mi++)
                    LDSM4(Af[mi][0], Af[mi][1], Af[mi][2], Af[mi][3],
                          st + aBase + mi * 16 * ROWB + k2 * 32);
                #pragma unroll
                for (int g = 0; g < 4; g++)
                    LDSM4(Bf[g][0], Bf[g][1], Bf[g][2], Bf[g][3],
                          st + bBase + g * 16 * ROWB + k2 * 32);
                #pragma unroll
                for (int mi = 0; mi < 4; mi++)
                    #pragma unroll
                    for (int g = 0; g < 4; g++) {
                        MMA16816(acc[mi][2*g],   Af[mi][0],Af[mi][1],Af[mi][2],Af[mi][3], Bf[g][0], Bf[g][2]);
                        MMA16816(acc[mi][2*g+1], Af[mi][0],Af[mi][1],Af[mi][2],Af[mi][3], Bf[g][1], Bf[g][3]);
                    }
            }
            if (ks + NST - 1 < KSTG) {
                const uint32_t st2 = sbase + ((ks + NST - 1) & (NST - 1)) * STAGE_BYTES;
                const int k0 = (ks + NST - 1) * KS;
                #pragma unroll
                for (int j = 0; j < 6; j++) {
                    const int row = prow[j], ch = pchk[j];
                    const __nv_bfloat16* g = (row < MT)
                        ? g_in_bf + (size_t)(m0 + row) * KDIM + k0 + ch * 8
                        : g_w_bf + (size_t)(vcol0 + row - MT) * KDIM + k0 + ch * 8;
                    cp_async16(st2 + (uint32_t)row * ROWB + ch * 16, g);
                }
            }
            CP_COMMIT();
        }

        // register-resident online logsumexp over this tile's 16 cols/lane/row
        #pragma unroll
        for (int mi = 0; mi < 4; mi++)
            #pragma unroll
            for (int h = 0; h < 2; h++) {
                const int ri = mi * 2 + h;
                float vmax = -FLT_MAX;
                #pragma unroll
                for (int nj = 0; nj < 8; nj++) {
                    vmax = fmaxf(vmax, acc[mi][nj][h * 2]);
                    vmax = fmaxf(vmax, acc[mi][nj][h * 2 + 1]);
                }
                const float nm = fmaxf(rmax[ri], vmax);
                float s = 0.f;
                #pragma unroll
                for (int nj = 0; nj < 8; nj++) {
                    s += __expf(acc[mi][nj][h * 2]     - nm);
                    s += __expf(acc[mi][nj][h * 2 + 1] - nm);
                }
                rsum[ri] = rsum[ri] * __expf(rmax[ri] - nm) + s;
                rmax[ri] = nm;
                const int dt = tgtr[ri] - vcol0;
                if (dt >= 0 && dt < NTILE) {
                    #pragma unroll
                    for (int nj = 0; nj < 8; nj++) {
                        const int c0 = wn * 64 + (nj >> 1) * 16 + (nj & 1) * 8 + lq * 2;
                        if (dt == c0)     tlog[ri] = acc[mi][nj][h * 2];
                        if (dt == c0 + 1) tlog[ri] = acc[mi][nj][h * 2 + 1];
                    }
                }
            }
    }

    // merge lanes with same rows (xor 1, 2 over lq)
    #pragma unroll
    for (int ri = 0; ri < 8; ri++) {
        #pragma unroll
        for (int off = 1; off < 4; off <<= 1) {
            const float om = __shfl_xor_sync(0xFFFFFFFFu, rmax[ri], off);
            const float os = __shfl_xor_sync(0xFFFFFFFFu, rsum[ri], off);
            const float nm = fmaxf(rmax[ri], om);
            rsum[ri] = rsum[ri] * __expf(rmax[ri] - nm) + os * __expf(om - nm);
            rmax[ri] = nm;
            tlog[ri] += __shfl_xor_sync(0xFFFFFFFFu, tlog[ri], off);
        }
    }
    // cross-warp merge over the 4 wn columns
    if (lq == 0) {
        #pragma unroll
        for (int ri = 0; ri < 8; ri++) {
            const int row = wm * 64 + (ri >> 1) * 16 + (ri & 1) * 8 + rq;
            smax[wn][row] = rmax[ri];
            ssum[wn][row] = rsum[ri];
            stl[wn][row]  = tlog[ri];
        }
    }
    __syncthreads();
    if (tid < MT) {
        float M = smax[0][tid];
        #pragma unroll
        for (int w = 1; w < 4; w++) M = fmaxf(M, smax[w][tid]);
        float S = 0.f, T = 0.f;
        #pragma unroll
        for (int w = 0; w < 4; w++) { S += ssum[w][tid] * __expf(smax[w][tid] - M); T += stl[w][tid]; }
        g_pmax[vs * N_TOK + m0 + tid] = M;
        g_psum[vs * N_TOK + m0 + tid] = S;
        const int t = target[m0 + tid];
        if (t >= vstart * NTILE && t < (vstart + ntiles) * NTILE)
            g_tlog[m0 + tid] = T;
    }
}

// -------- combine splits per row, block-sum NLL --------
__global__ void reduce1_kernel(const int* __restrict__ target) {
    const int r = blockIdx.x * 128 + threadIdx.x;
    float M = -FLT_MAX;
    #pragma unroll
    for (int s = 0; s < VSPLIT; s++) M = fmaxf(M, g_pmax[s * N_TOK + r]);
    float S = 0.f;
    #pragma unroll
    for (int s = 0; s < VSPLIT; s++) S += g_psum[s * N_TOK + r] * __expf(g_pmax[s * N_TOK + r] - M);
    int t = target[r];
    int valid = (t != -100);
    float nll = valid ? (M + logf(S) - g_tlog[r]) : 0.f;

    __shared__ float sh[128];
    __shared__ int   sc[128];
    sh[threadIdx.x] = nll; sc[threadIdx.x] = valid;
    __syncthreads();
    for (int o = 64; o > 0; o >>= 1) {
        if (threadIdx.x < o) { sh[threadIdx.x] += sh[threadIdx.x + o]; sc[threadIdx.x] += sc[threadIdx.x + o]; }
        __syncthreads();
    }
    if (threadIdx.x == 0) { g_bnll[blockIdx.x] = sh[0]; g_bcnt[blockIdx.x] = sc[0]; }
}

__global__ void reduce2_kernel(float* __restrict__ out) {
    __shared__ float sh[64];
    __shared__ int   sc[64];
    int t = threadIdx.x;
    sh[t] = g_bnll[t]; sc[t] = g_bcnt[t];
    __syncthreads();
    for (int o = 32; o > 0; o >>= 1) {
        if (t < o) { sh[t] += sh[t + o]; sc[t] += sc[t + o]; }
        __syncthreads();
    }
    if (t == 0) {
        int c = sc[0] > 0 ? sc[0] : 1;
        out[0] = sh[0] / (float)c;
    }
}

extern "C" void kernel_launch(void* const* d_in, const int* in_sizes, int n_in,
                              void* d_out, int out_size) {
    const float* input  = (const float*)d_in[0];   // [8192,4096] f32
    const float* weight = (const float*)d_in[1];   // [32000,4096] f32
    const int* target   = (const int*)d_in[2];     // [8192] int32
    float* out = (float*)d_out;

    cudaFuncSetAttribute(lmhead_mma, cudaFuncAttributeMaxDynamicSharedMemorySize, SMEM_DYN);

    cvt_kernel<<<4096, 256>>>(input,  (size_t)N_TOK * KDIM / 4, 0);
    cvt_kernel<<<8192, 256>>>(weight, (size_t)VDIM * KDIM / 4, 1);

    dim3 grid(MBLK, VSPLIT);
    lmhead_mma<<<grid, 256, SMEM_DYN>>>(target);

    reduce1_kernel<<<MBLK, 128>>>(target);
    reduce2_kernel<<<1, 64>>>(out);
}

// round 9
// speedup vs baseline: 5.6195x; 1.0704x over previous
#include <cuda_runtime.h>
#include <cuda_bf16.h>
#include <cfloat>
#include <math.h>
#include <stdint.h>

#define N_TOK 8192
#define KDIM  4096
#define VDIM  32000
#define MT    128
#define NTILE 256
#define KS    32                   // K elems per stage
#define NST   4                    // cp.async stages
#define KSTG  (KDIM / KS)          // 128
#define NVT   (VDIM / NTILE)       // 125
#define VSPLIT 2
#define VS0   63                   // tiles in split 0 (split 1: 62)
#define MBLK  (N_TOK / MT)         // 64
#define NTHREADS 512
#define ROWB  80                   // padded smem row: 32 K-elems (64B) + 16B pad
#define A_BYTES (MT * ROWB)        // 10240
#define STAGE_BYTES ((MT + NTILE) * ROWB)      // 30720
#define SMEM_DYN (NST * STAGE_BYTES)           // 122880

// -------- device scratch --------
__device__ __nv_bfloat16 g_in_bf[(size_t)N_TOK * KDIM];
__device__ __nv_bfloat16 g_w_bf[(size_t)VDIM * KDIM];
__device__ float g_pmax[VSPLIT * N_TOK];
__device__ float g_psum[VSPLIT * N_TOK];
__device__ float g_tlog[N_TOK];
__device__ float g_bnll[MBLK];
__device__ int   g_bcnt[MBLK];

// -------- helpers --------
__device__ __forceinline__ uint32_t smem_u32(const void* p) {
    uint32_t a;
    asm("{ .reg .u64 t; cvta.to.shared.u64 t, %1; cvt.u32.u64 %0, t; }" : "=r"(a) : "l"(p));
    return a;
}
__device__ __forceinline__ void cp_async16(uint32_t sa, const void* g) {
    asm volatile("cp.async.cg.shared.global [%0], [%1], 16;" :: "r"(sa), "l"(g));
}
#define CP_COMMIT() asm volatile("cp.async.commit_group;" ::: "memory")
#define CP_WAIT(n)  asm volatile("cp.async.wait_group %0;" :: "n"(n) : "memory")

#define LDSM4(d0,d1,d2,d3,addr) \
    asm volatile("ldmatrix.sync.aligned.m8n8.x4.shared.b16 {%0,%1,%2,%3}, [%4];" \
        : "=r"(d0),"=r"(d1),"=r"(d2),"=r"(d3) : "r"(addr))

#define MMA16816(d,a0,a1,a2,a3,b0,b1) \
    asm volatile("mma.sync.aligned.m16n8k16.row.col.f32.bf16.bf16.f32 " \
        "{%0,%1,%2,%3},{%4,%5,%6,%7},{%8,%9},{%0,%1,%2,%3};" \
        : "+f"((d)[0]),"+f"((d)[1]),"+f"((d)[2]),"+f"((d)[3]) \
        : "r"(a0),"r"(a1),"r"(a2),"r"(a3),"r"(b0),"r"(b1))

// -------- fp32 -> bf16 conversion --------
__global__ void cvt_kernel(const float* __restrict__ src, size_t n4, int which) {
    __nv_bfloat16* dst = which ? g_w_bf : g_in_bf;
    uint2* d2 = reinterpret_cast<uint2*>(dst);
    const float4* s4 = reinterpret_cast<const float4*>(src);
    size_t i = (size_t)blockIdx.x * blockDim.x + threadIdx.x;
    size_t stride = (size_t)gridDim.x * blockDim.x;
    for (; i < n4; i += stride) {
        float4 v = s4[i];
        __nv_bfloat162 lo = __floats2bfloat162_rn(v.x, v.y);
        __nv_bfloat162 hi = __floats2bfloat162_rn(v.z, v.w);
        uint2 o;
        o.x = *reinterpret_cast<unsigned int*>(&lo);
        o.y = *reinterpret_cast<unsigned int*>(&hi);
        d2[i] = o;
    }
}

// -------- bf16 mma.sync GEMM + register-resident online logsumexp --------
// grid (64, 2), block 512 = 16 warps, warp grid 4(m) x 4(n), warp tile 32x64
__global__ void __launch_bounds__(NTHREADS, 1)
lmhead_mma(const int* __restrict__ target) {
    extern __shared__ __align__(128) unsigned char dsm[];
    __shared__ float smax[4][MT], ssum[4][MT], stl[4][MT];

    const int tid = threadIdx.x, lane = tid & 31, warp = tid >> 5;
    const int wm = warp & 3, wn = warp >> 2;   // wm 0..3 (m), wn 0..3 (n)
    const int m0 = blockIdx.x * MT;
    const int vs = blockIdx.y;
    const int vstart = vs ? VS0 : 0;
    const int ntiles = vs ? (NVT - VS0) : VS0;
    const uint32_t sbase = smem_u32(dsm);

    // producer mapping: 384 rows x 4 chunks(16B) = 1536 ids; 3 per thread
    int prow[3], pchk[3];
    #pragma unroll
    for (int j = 0; j < 3; j++) { const int id = tid + j * NTHREADS; prow[j] = id >> 2; pchk[j] = id & 3; }

    // ldmatrix base offsets
    const int l15 = lane & 15, lh = lane >> 4, lq = lane & 3, rq = lane >> 2;
    const uint32_t aBase = (uint32_t)(wm * 32 + l15) * ROWB + lh * 16;
    const uint32_t bBase = A_BYTES + (uint32_t)(wn * 64 + l15) * ROWB + lh * 16;

    // per-lane running logsumexp state: 4 rows/lane (2 m-frags x 2 halves)
    float rmax[4], rsum[4], tlog[4];
    int tgtr[4];
    #pragma unroll
    for (int i = 0; i < 4; i++) { rmax[i] = -FLT_MAX; rsum[i] = 0.f; tlog[i] = 0.f; }
    #pragma unroll
    for (int mi = 0; mi < 2; mi++)
        #pragma unroll
        for (int h = 0; h < 2; h++)
            tgtr[mi * 2 + h] = target[m0 + wm * 32 + mi * 16 + h * 8 + rq];

    for (int lt = 0; lt < ntiles; ++lt) {
        const int vcol0 = (vstart + lt) * NTILE;

        float acc[2][8][4];
        #pragma unroll
        for (int mi = 0; mi < 2; mi++)
            #pragma unroll
            for (int nj = 0; nj < 8; nj++)
                #pragma unroll
                for (int q = 0; q < 4; q++) acc[mi][nj][q] = 0.f;

        // prologue: stages 0..NST-2
        #pragma unroll
        for (int s = 0; s < NST - 1; s++) {
            const uint32_t st = sbase + s * STAGE_BYTES;
            const int k0 = s * KS;
            #pragma unroll
            for (int j = 0; j < 3; j++) {
                const int row = prow[j], ch = pchk[j];
                const __nv_bfloat16* g = (row < MT)
                    ? g_in_bf + (size_t)(m0 + row) * KDIM + k0 + ch * 8
                    : g_w_bf + (size_t)(vcol0 + row - MT) * KDIM + k0 + ch * 8;
                cp_async16(st + (uint32_t)row * ROWB + ch * 16, g);
            }
            CP_COMMIT();
        }

        #pragma unroll 1
        for (int ks = 0; ks < KSTG; ++ks) {
            CP_WAIT(NST - 2);
            __syncthreads();
            const uint32_t st = sbase + (ks & (NST - 1)) * STAGE_BYTES;
            #pragma unroll
            for (int k2 = 0; k2 < 2; k2++) {
                uint32_t Af[2][4], Bf[4][4];
                #pragma unroll
                for (int mi = 0; mi < 2; mi++)
                    LDSM4(Af[mi][0], Af[mi][1], Af[mi][2], Af[mi][3],
                          st + aBase + mi * 16 * ROWB + k2 * 32);
                #pragma unroll
                for (int g = 0; g < 4; g++)
                    LDSM4(Bf[g][0], Bf[g][1], Bf[g][2], Bf[g][3],
                          st + bBase + g * 16 * ROWB + k2 * 32);
                #pragma unroll
                for (int mi = 0; mi < 2; mi++)
                    #pragma unroll
                    for (int g = 0; g < 4; g++) {
                        MMA16816(acc[mi][2*g],   Af[mi][0],Af[mi][1],Af[mi][2],Af[mi][3], Bf[g][0], Bf[g][2]);
                        MMA16816(acc[mi][2*g+1], Af[mi][0],Af[mi][1],Af[mi][2],Af[mi][3], Bf[g][1], Bf[g][3]);
                    }
            }
            if (ks + NST - 1 < KSTG) {
                const uint32_t st2 = sbase + ((ks + NST - 1) & (NST - 1)) * STAGE_BYTES;
                const int k0 = (ks + NST - 1) * KS;
                #pragma unroll
                for (int j = 0; j < 3; j++) {
                    const int row = prow[j], ch = pchk[j];
                    const __nv_bfloat16* g = (row < MT)
                        ? g_in_bf + (size_t)(m0 + row) * KDIM + k0 + ch * 8
                        : g_w_bf + (size_t)(vcol0 + row - MT) * KDIM + k0 + ch * 8;
                    cp_async16(st2 + (uint32_t)row * ROWB + ch * 16, g);
                }
            }
            CP_COMMIT();
        }

        // register-resident online logsumexp over this tile's 16 cols/lane/row
        #pragma unroll
        for (int mi = 0; mi < 2; mi++)
            #pragma unroll
            for (int h = 0; h < 2; h++) {
                const int ri = mi * 2 + h;
                float vmax = -FLT_MAX;
                #pragma unroll
                for (int nj = 0; nj < 8; nj++) {
                    vmax = fmaxf(vmax, acc[mi][nj][h * 2]);
                    vmax = fmaxf(vmax, acc[mi][nj][h * 2 + 1]);
                }
                const float nm = fmaxf(rmax[ri], vmax);
                float s = 0.f;
                #pragma unroll
                for (int nj = 0; nj < 8; nj++) {
                    s += __expf(acc[mi][nj][h * 2]     - nm);
                    s += __expf(acc[mi][nj][h * 2 + 1] - nm);
                }
                rsum[ri] = rsum[ri] * __expf(rmax[ri] - nm) + s;
                rmax[ri] = nm;
                const int dt = tgtr[ri] - vcol0;
                if (dt >= 0 && dt < NTILE) {
                    #pragma unroll
                    for (int nj = 0; nj < 8; nj++) {
                        const int c0 = wn * 64 + (nj >> 1) * 16 + (nj & 1) * 8 + lq * 2;
                        if (dt == c0)     tlog[ri] = acc[mi][nj][h * 2];
                        if (dt == c0 + 1) tlog[ri] = acc[mi][nj][h * 2 + 1];
                    }
                }
            }
    }

    // merge lanes with same rows (xor 1, 2 over lq)
    #pragma unroll
    for (int ri = 0; ri < 4; ri++) {
        #pragma unroll
        for (int off = 1; off < 4; off <<= 1) {
            const float om = __shfl_xor_sync(0xFFFFFFFFu, rmax[ri], off);
            const float os = __shfl_xor_sync(0xFFFFFFFFu, rsum[ri], off);
            const float nm = fmaxf(rmax[ri], om);
            rsum[ri] = rsum[ri] * __expf(rmax[ri] - nm) + os * __expf(om - nm);
            rmax[ri] = nm;
            tlog[ri] += __shfl_xor_sync(0xFFFFFFFFu, tlog[ri], off);
        }
    }
    // cross-warp merge over the 4 wn columns (same wm share rows)
    if (lq == 0) {
        #pragma unroll
        for (int ri = 0; ri < 4; ri++) {
            const int row = wm * 32 + (ri >> 1) * 16 + (ri & 1) * 8 + rq;
            smax[wn][row] = rmax[ri];
            ssum[wn][row] = rsum[ri];
            stl[wn][row]  = tlog[ri];
        }
    }
    __syncthreads();
    if (tid < MT) {
        float M = smax[0][tid];
        #pragma unroll
        for (int w = 1; w < 4; w++) M = fmaxf(M, smax[w][tid]);
        float S = 0.f, T = 0.f;
        #pragma unroll
        for (int w = 0; w < 4; w++) { S += ssum[w][tid] * __expf(smax[w][tid] - M); T += stl[w][tid]; }
        g_pmax[vs * N_TOK + m0 + tid] = M;
        g_psum[vs * N_TOK + m0 + tid] = S;
        const int t = target[m0 + tid];
        if (t >= vstart * NTILE && t < (vstart + ntiles) * NTILE)
            g_tlog[m0 + tid] = T;
    }
}

// -------- combine splits per row, block-sum NLL --------
__global__ void reduce1_kernel(const int* __restrict__ target) {
    const int r = blockIdx.x * 128 + threadIdx.x;
    float M = -FLT_MAX;
    #pragma unroll
    for (int s = 0; s < VSPLIT; s++) M = fmaxf(M, g_pmax[s * N_TOK + r]);
    float S = 0.f;
    #pragma unroll
    for (int s = 0; s < VSPLIT; s++) S += g_psum[s * N_TOK + r] * __expf(g_pmax[s * N_TOK + r] - M);
    int t = target[r];
    int valid = (t != -100);
    float nll = valid ? (M + logf(S) - g_tlog[r]) : 0.f;

    __shared__ float sh[128];
    __shared__ int   sc[128];
    sh[threadIdx.x] = nll; sc[threadIdx.x] = valid;
    __syncthreads();
    for (int o = 64; o > 0; o >>= 1) {
        if (threadIdx.x < o) { sh[threadIdx.x] += sh[threadIdx.x + o]; sc[threadIdx.x] += sc[threadIdx.x + o]; }
        __syncthreads();
    }
    if (threadIdx.x == 0) { g_bnll[blockIdx.x] = sh[0]; g_bcnt[blockIdx.x] = sc[0]; }
}

__global__ void reduce2_kernel(float* __restrict__ out) {
    __shared__ float sh[64];
    __shared__ int   sc[64];
    int t = threadIdx.x;
    sh[t] = g_bnll[t]; sc[t] = g_bcnt[t];
    __syncthreads();
    for (int o = 32; o > 0; o >>= 1) {
        if (t < o) { sh[t] += sh[t + o]; sc[t] += sc[t + o]; }
        __syncthreads();
    }
    if (t == 0) {
        int c = sc[0] > 0 ? sc[0] : 1;
        out[0] = sh[0] / (float)c;
    }
}

extern "C" void kernel_launch(void* const* d_in, const int* in_sizes, int n_in,
                              void* d_out, int out_size) {
    const float* input  = (const float*)d_in[0];   // [8192,4096] f32
    const float* weight = (const float*)d_in[1];   // [32000,4096] f32
    const int* target   = (const int*)d_in[2];     // [8192] int32
    float* out = (float*)d_out;

    cudaFuncSetAttribute(lmhead_mma, cudaFuncAttributeMaxDynamicSharedMemorySize, SMEM_DYN);

    cvt_kernel<<<4096, 256>>>(input,  (size_t)N_TOK * KDIM / 4, 0);
    cvt_kernel<<<8192, 256>>>(weight, (size_t)VDIM * KDIM / 4, 1);

    dim3 grid(MBLK, VSPLIT);
    lmhead_mma<<<grid, NTHREADS, SMEM_DYN>>>(target);

    reduce1_kernel<<<MBLK, 128>>>(target);
    reduce2_kernel<<<1, 64>>>(out);
}

// round 13
// speedup vs baseline: 5.6719x; 1.0093x over previous
#include <cuda_runtime.h>
#include <cuda_bf16.h>
#include <cfloat>
#include <math.h>
#include <stdint.h>

#define N_TOK 8192
#define KDIM  4096
#define VDIM  32000
#define MT    128
#define NTILE 256
#define KS    64                   // K elems per stage
#define NST   3                    // cp.async stages
#define KSTG  (KDIM / KS)          // 64
#define NVT   (VDIM / NTILE)       // 125
#define VSPLIT 2
#define VS0   63                   // tiles in split 0 (split 1: 62)
#define MBLK  (N_TOK / MT)         // 64
#define NTHREADS 512
#define ROWB  144                  // 64 bf16 (128B) + 16B pad; ldmatrix conflict-free
#define A_BYTES (MT * ROWB)        // 18432
#define STAGE_BYTES ((MT + NTILE) * ROWB)      // 55296
#define SMEM_DYN (NST * STAGE_BYTES)           // 165888

// -------- device scratch --------
__device__ __nv_bfloat16 g_in_bf[(size_t)N_TOK * KDIM];
__device__ __nv_bfloat16 g_w_bf[(size_t)VDIM * KDIM];
__device__ float g_pmax[VSPLIT * N_TOK];
__device__ float g_psum[VSPLIT * N_TOK];
__device__ float g_tlog[N_TOK];
__device__ float g_bnll[MBLK];
__device__ int   g_bcnt[MBLK];

// -------- helpers --------
__device__ __forceinline__ uint32_t smem_u32(const void* p) {
    uint32_t a;
    asm("{ .reg .u64 t; cvta.to.shared.u64 t, %1; cvt.u32.u64 %0, t; }" : "=r"(a) : "l"(p));
    return a;
}
__device__ __forceinline__ void cp_async16(uint32_t sa, const void* g) {
    asm volatile("cp.async.cg.shared.global [%0], [%1], 16;" :: "r"(sa), "l"(g));
}
#define CP_COMMIT() asm volatile("cp.async.commit_group;" ::: "memory")
#define CP_WAIT(n)  asm volatile("cp.async.wait_group %0;" :: "n"(n) : "memory")

#define LDSM4(d0,d1,d2,d3,addr) \
    asm volatile("ldmatrix.sync.aligned.m8n8.x4.shared.b16 {%0,%1,%2,%3}, [%4];" \
        : "=r"(d0),"=r"(d1),"=r"(d2),"=r"(d3) : "r"(addr))

#define MMA16816(d,a0,a1,a2,a3,b0,b1) \
    asm volatile("mma.sync.aligned.m16n8k16.row.col.f32.bf16.bf16.f32 " \
        "{%0,%1,%2,%3},{%4,%5,%6,%7},{%8,%9},{%0,%1,%2,%3};" \
        : "+f"((d)[0]),"+f"((d)[1]),"+f"((d)[2]),"+f"((d)[3]) \
        : "r"(a0),"r"(a1),"r"(a2),"r"(a3),"r"(b0),"r"(b1))

// -------- fp32 -> bf16 conversion --------
__global__ void cvt_kernel(const float* __restrict__ src, size_t n4, int which) {
    __nv_bfloat16* dst = which ? g_w_bf : g_in_bf;
    uint2* d2 = reinterpret_cast<uint2*>(dst);
    const float4* s4 = reinterpret_cast<const float4*>(src);
    size_t i = (size_t)blockIdx.x * blockDim.x + threadIdx.x;
    size_t stride = (size_t)gridDim.x * blockDim.x;
    for (; i < n4; i += stride) {
        float4 v = s4[i];
        __nv_bfloat162 lo = __floats2bfloat162_rn(v.x, v.y);
        __nv_bfloat162 hi = __floats2bfloat162_rn(v.z, v.w);
        uint2 o;
        o.x = *reinterpret_cast<unsigned int*>(&lo);
        o.y = *reinterpret_cast<unsigned int*>(&hi);
        d2[i] = o;
    }
}

// stage fill: each thread issues 6 cp.async16 (3072 chunks / 512 threads)
__device__ __forceinline__ void fill_stage(uint32_t st, int m0, int vcol0, int k0,
                                           const int* prow, const int* pchk) {
    #pragma unroll
    for (int j = 0; j < 6; j++) {
        const int row = prow[j], ch = pchk[j];
        const __nv_bfloat16* g = (row < MT)
            ? g_in_bf + (size_t)(m0 + row) * KDIM + k0 + ch * 8
            : g_w_bf + (size_t)(vcol0 + row - MT) * KDIM + k0 + ch * 8;
        cp_async16(st + (uint32_t)row * ROWB + ch * 16, g);
    }
    CP_COMMIT();
}

// -------- bf16 mma.sync GEMM + register-resident online logsumexp --------
// grid (64, 2), block 512 = 16 warps, warp grid 4(m) x 4(n), warp tile 32x64
__global__ void __launch_bounds__(NTHREADS, 1)
lmhead_mma(const int* __restrict__ target) {
    extern __shared__ __align__(128) unsigned char dsm[];
    __shared__ float smax[4][MT], ssum[4][MT], stl[4][MT];

    const int tid = threadIdx.x, lane = tid & 31, warp = tid >> 5;
    const int wm = warp & 3, wn = warp >> 2;
    const int m0 = blockIdx.x * MT;
    const int vs = blockIdx.y;
    const int vstart = vs ? VS0 : 0;
    const int ntiles = vs ? (NVT - VS0) : VS0;
    const int niter = ntiles * KSTG;
    const uint32_t sbase = smem_u32(dsm);

    // producer mapping: 384 rows x 8 chunks(16B) = 3072 ids; 6 per thread
    int prow[6], pchk[6];
    #pragma unroll
    for (int j = 0; j < 6; j++) { const int id = tid + j * NTHREADS; prow[j] = id >> 3; pchk[j] = id & 7; }

    // ldmatrix base offsets
    const int l15 = lane & 15, lh = lane >> 4, lq = lane & 3, rq = lane >> 2;
    const uint32_t aBase = (uint32_t)(wm * 32 + l15) * ROWB + lh * 16;
    const uint32_t bBase = A_BYTES + (uint32_t)(wn * 64 + l15) * ROWB + lh * 16;

    // per-lane running logsumexp state: 4 rows/lane
    float rmax[4], rsum[4], tlog[4];
    int tgtr[4];
    #pragma unroll
    for (int i = 0; i < 4; i++) { rmax[i] = -FLT_MAX; rsum[i] = 0.f; tlog[i] = 0.f; }
    #pragma unroll
    for (int mi = 0; mi < 2; mi++)
        #pragma unroll
        for (int h = 0; h < 2; h++)
            tgtr[mi * 2 + h] = target[m0 + wm * 32 + mi * 16 + h * 8 + rq];

    float acc[2][8][4];
    #pragma unroll
    for (int mi = 0; mi < 2; mi++)
        #pragma unroll
        for (int nj = 0; nj < 8; nj++)
            #pragma unroll
            for (int q = 0; q < 4; q++) acc[mi][nj][q] = 0.f;

    // single prologue: stages 0..NST-2
    #pragma unroll
    for (int s = 0; s < NST - 1; s++) {
        const int t2 = s >> 6 < ntiles ? (s / KSTG) : 0;   // s < KSTG always here
        fill_stage(sbase + s * STAGE_BYTES, m0, (vstart + t2) * NTILE, (s % KSTG) * KS, prow, pchk);
    }

    for (int it = 0; it < niter; ++it) {
        CP_WAIT(NST - 2);
        __syncthreads();
        const uint32_t st = sbase + (it % NST) * STAGE_BYTES;

        #pragma unroll
        for (int k2 = 0; k2 < 4; k2++) {
            uint32_t Af[2][4], Bf[4][4];
            #pragma unroll
            for (int mi = 0; mi < 2; mi++)
                LDSM4(Af[mi][0], Af[mi][1], Af[mi][2], Af[mi][3],
                      st + aBase + mi * 16 * ROWB + k2 * 32);
            #pragma unroll
            for (int g = 0; g < 4; g++)
                LDSM4(Bf[g][0], Bf[g][1], Bf[g][2], Bf[g][3],
                      st + bBase + g * 16 * ROWB + k2 * 32);
            #pragma unroll
            for (int mi = 0; mi < 2; mi++)
                #pragma unroll
                for (int g = 0; g < 4; g++) {
                    MMA16816(acc[mi][2*g],   Af[mi][0],Af[mi][1],Af[mi][2],Af[mi][3], Bf[g][0], Bf[g][2]);
                    MMA16816(acc[mi][2*g+1], Af[mi][0],Af[mi][1],Af[mi][2],Af[mi][3], Bf[g][1], Bf[g][3]);
                }
        }

        // prefetch stage it+NST-1
        const int pit = it + NST - 1;
        if (pit < niter) {
            const int t2 = pit / KSTG;
            fill_stage(sbase + (pit % NST) * STAGE_BYTES, m0,
                       (vstart + t2) * NTILE, (pit % KSTG) * KS, prow, pchk);
        } else {
            CP_COMMIT();   // keep group count in lockstep
        }

        // per-tile epilogue after last kstage of each tile
        if ((it & (KSTG - 1)) == KSTG - 1) {
            const int vcol0 = (vstart + it / KSTG) * NTILE;
            #pragma unroll
            for (int mi = 0; mi < 2; mi++)
                #pragma unroll
                for (int h = 0; h < 2; h++) {
                    const int ri = mi * 2 + h;
                    float vmax = -FLT_MAX;
                    #pragma unroll
                    for (int nj = 0; nj < 8; nj++) {
                        vmax = fmaxf(vmax, acc[mi][nj][h * 2]);
                        vmax = fmaxf(vmax, acc[mi][nj][h * 2 + 1]);
                    }
                    const float nm = fmaxf(rmax[ri], vmax);
                    float s = 0.f;
                    #pragma unroll
                    for (int nj = 0; nj < 8; nj++) {
                        s += __expf(acc[mi][nj][h * 2]     - nm);
                        s += __expf(acc[mi][nj][h * 2 + 1] - nm);
                    }
                    rsum[ri] = rsum[ri] * __expf(rmax[ri] - nm) + s;
                    rmax[ri] = nm;
                    const int dt = tgtr[ri] - vcol0;
                    if (dt >= 0 && dt < NTILE) {
                        #pragma unroll
                        for (int nj = 0; nj < 8; nj++) {
                            const int c0 = wn * 64 + (nj >> 1) * 16 + (nj & 1) * 8 + lq * 2;
                            if (dt == c0)     tlog[ri] = acc[mi][nj][h * 2];
                            if (dt == c0 + 1) tlog[ri] = acc[mi][nj][h * 2 + 1];
                        }
                    }
                    #pragma unroll
                    for (int nj = 0; nj < 8; nj++) {
                        acc[mi][nj][h * 2] = 0.f; acc[mi][nj][h * 2 + 1] = 0.f;
                    }
                }
        }
    }

    // merge lanes with same rows (xor 1, 2 over lq)
    #pragma unroll
    for (int ri = 0; ri < 4; ri++) {
        #pragma unroll
        for (int off = 1; off < 4; off <<= 1) {
            const float om = __shfl_xor_sync(0xFFFFFFFFu, rmax[ri], off);
            const float os = __shfl_xor_sync(0xFFFFFFFFu, rsum[ri], off);
            const float nm = fmaxf(rmax[ri], om);
            rsum[ri] = rsum[ri] * __expf(rmax[ri] - nm) + os * __expf(om - nm);
            rmax[ri] = nm;
            tlog[ri] += __shfl_xor_sync(0xFFFFFFFFu, tlog[ri], off);
        }
    }
    // cross-warp merge over the 4 wn columns
    if (lq == 0) {
        #pragma unroll
        for (int ri = 0; ri < 4; ri++) {
            const int row = wm * 32 + (ri >> 1) * 16 + (ri & 1) * 8 + rq;
            smax[wn][row] = rmax[ri];
            ssum[wn][row] = rsum[ri];
            stl[wn][row]  = tlog[ri];
        }
    }
    __syncthreads();
    if (tid < MT) {
        float M = smax[0][tid];
        #pragma unroll
        for (int w = 1; w < 4; w++) M = fmaxf(M, smax[w][tid]);
        float S = 0.f, T = 0.f;
        #pragma unroll
        for (int w = 0; w < 4; w++) { S += ssum[w][tid] * __expf(smax[w][tid] - M); T += stl[w][tid]; }
        g_pmax[vs * N_TOK + m0 + tid] = M;
        g_psum[vs * N_TOK + m0 + tid] = S;
        const int t = target[m0 + tid];
        if (t >= vstart * NTILE && t < (vstart + ntiles) * NTILE)
            g_tlog[m0 + tid] = T;
    }
}

// -------- combine splits per row, block-sum NLL --------
__global__ void reduce1_kernel(const int* __restrict__ target) {
    const int r = blockIdx.x * 128 + threadIdx.x;
    float M = -FLT_MAX;
    #pragma unroll
    for (int s = 0; s < VSPLIT; s++) M = fmaxf(M, g_pmax[s * N_TOK + r]);
    float S = 0.f;
    #pragma unroll
    for (int s = 0; s < VSPLIT; s++) S += g_psum[s * N_TOK + r] * __expf(g_pmax[s * N_TOK + r] - M);
    int t = target[r];
    int valid = (t != -100);
    float nll = valid ? (M + logf(S) - g_tlog[r]) : 0.f;

    __shared__ float sh[128];
    __shared__ int   sc[128];
    sh[threadIdx.x] = nll; sc[threadIdx.x] = valid;
    __syncthreads();
    for (int o = 64; o > 0; o >>= 1) {
        if (threadIdx.x < o) { sh[threadIdx.x] += sh[threadIdx.x + o]; sc[threadIdx.x] += sc[threadIdx.x + o]; }
        __syncthreads();
    }
    if (threadIdx.x == 0) { g_bnll[blockIdx.x] = sh[0]; g_bcnt[blockIdx.x] = sc[0]; }
}

__global__ void reduce2_kernel(float* __restrict__ out) {
    __shared__ float sh[64];
    __shared__ int   sc[64];
    int t = threadIdx.x;
    sh[t] = g_bnll[t]; sc[t] = g_bcnt[t];
    __syncthreads();
    for (int o = 32; o > 0; o >>= 1) {
        if (t < o) { sh[t] += sh[t + o]; sc[t] += sc[t + o]; }
        __syncthreads();
    }
    if (t == 0) {
        int c = sc[0] > 0 ? sc[0] : 1;
        out[0] = sh[0] / (float)c;
    }
}

extern "C" void kernel_launch(void* const* d_in, const int* in_sizes, int n_in,
                              void* d_out, int out_size) {
    const float* input  = (const float*)d_in[0];   // [8192,4096] f32
    const float* weight = (const float*)d_in[1];   // [32000,4096] f32
    const int* target   = (const int*)d_in[2];     // [8192] int32
    float* out = (float*)d_out;

    cudaFuncSetAttribute(lmhead_mma, cudaFuncAttributeMaxDynamicSharedMemorySize, SMEM_DYN);

    cvt_kernel<<<4096, 256>>>(input,  (size_t)N_TOK * KDIM / 4, 0);
    cvt_kernel<<<8192, 256>>>(weight, (size_t)VDIM * KDIM / 4, 1);

    dim3 grid(MBLK, VSPLIT);
    lmhead_mma<<<grid, NTHREADS, SMEM_DYN>>>(target);

    reduce1_kernel<<<MBLK, 128>>>(target);
    reduce2_kernel<<<1, 64>>>(out);
}

// round 14
// speedup vs baseline: 6.4966x; 1.1454x over previous
#include <cuda_runtime.h>
#include <cuda_bf16.h>
#include <cfloat>
#include <math.h>
#include <stdint.h>

#define N_TOK 8192
#define KDIM  4096
#define VDIM  32000
#define MT    128
#define NTILE 256
#define KS    64                   // K elems per stage
#define NST   4                    // cp.async stages
#define KSTG  (KDIM / KS)          // 64
#define NVT   (VDIM / NTILE)       // 125
#define NGRP  25                   // v-groups (uniform)
#define TPG   (NVT / NGRP)         // 5 tiles per group
#define MBLK  (N_TOK / MT)         // 64
#define NJOBS (MBLK * NGRP)        // 1600
#define NTHREADS 512
#define ROWB  144                  // 64 bf16 (128B) + 16B pad; ldmatrix conflict-free
#define A_BYTES (MT * ROWB)        // 18432
#define STAGE_BYTES ((MT + NTILE) * ROWB)      // 55296
#define SMEM_DYN (NST * STAGE_BYTES)           // 221184

// -------- device scratch --------
__device__ __nv_bfloat16 g_in_bf[(size_t)N_TOK * KDIM];
__device__ __nv_bfloat16 g_w_bf[(size_t)VDIM * KDIM];
__device__ float g_pmax[NGRP * N_TOK];
__device__ float g_psum[NGRP * N_TOK];
__device__ float g_tlog[N_TOK];
__device__ float g_bnll[MBLK];
__device__ int   g_bcnt[MBLK];

// -------- helpers --------
__device__ __forceinline__ uint32_t smem_u32(const void* p) {
    uint32_t a;
    asm("{ .reg .u64 t; cvta.to.shared.u64 t, %1; cvt.u32.u64 %0, t; }" : "=r"(a) : "l"(p));
    return a;
}
__device__ __forceinline__ void cp_async16(uint32_t sa, const void* g) {
    asm volatile("cp.async.cg.shared.global [%0], [%1], 16;" :: "r"(sa), "l"(g));
}
#define CP_COMMIT() asm volatile("cp.async.commit_group;" ::: "memory")
#define CP_WAIT(n)  asm volatile("cp.async.wait_group %0;" :: "n"(n) : "memory")

#define LDSM4(d0,d1,d2,d3,addr) \
    asm volatile("ldmatrix.sync.aligned.m8n8.x4.shared.b16 {%0,%1,%2,%3}, [%4];" \
        : "=r"(d0),"=r"(d1),"=r"(d2),"=r"(d3) : "r"(addr))

#define MMA16816(d,a0,a1,a2,a3,b0,b1) \
    asm volatile("mma.sync.aligned.m16n8k16.row.col.f32.bf16.bf16.f32 " \
        "{%0,%1,%2,%3},{%4,%5,%6,%7},{%8,%9},{%0,%1,%2,%3};" \
        : "+f"((d)[0]),"+f"((d)[1]),"+f"((d)[2]),"+f"((d)[3]) \
        : "r"(a0),"r"(a1),"r"(a2),"r"(a3),"r"(b0),"r"(b1))

// -------- fp32 -> bf16 conversion --------
__global__ void cvt_kernel(const float* __restrict__ src, size_t n4, int which) {
    __nv_bfloat16* dst = which ? g_w_bf : g_in_bf;
    uint2* d2 = reinterpret_cast<uint2*>(dst);
    const float4* s4 = reinterpret_cast<const float4*>(src);
    size_t i = (size_t)blockIdx.x * blockDim.x + threadIdx.x;
    size_t stride = (size_t)gridDim.x * blockDim.x;
    for (; i < n4; i += stride) {
        float4 v = s4[i];
        __nv_bfloat162 lo = __floats2bfloat162_rn(v.x, v.y);
        __nv_bfloat162 hi = __floats2bfloat162_rn(v.z, v.w);
        uint2 o;
        o.x = *reinterpret_cast<unsigned int*>(&lo);
        o.y = *reinterpret_cast<unsigned int*>(&hi);
        d2[i] = o;
    }
}

// stage fill: each thread issues 6 cp.async16 (3072 chunks / 512 threads)
__device__ __forceinline__ void fill_stage(uint32_t st, int m0, int vcol0, int k0,
                                           const int* prow, const int* pchk) {
    #pragma unroll
    for (int j = 0; j < 6; j++) {
        const int row = prow[j], ch = pchk[j];
        const __nv_bfloat16* g = (row < MT)
            ? g_in_bf + (size_t)(m0 + row) * KDIM + k0 + ch * 8
            : g_w_bf + (size_t)(vcol0 + row - MT) * KDIM + k0 + ch * 8;
        cp_async16(st + (uint32_t)row * ROWB + ch * 16, g);
    }
    CP_COMMIT();
}

// -------- persistent bf16 mma.sync GEMM + register-resident online logsumexp --------
// grid = #SMs, block 512 = 16 warps, warp grid 4(m) x 4(n), warp tile 32x64
// jobs: 64 m-blocks x 25 v-groups (5 tiles each), statically interleaved
__global__ void __launch_bounds__(NTHREADS, 1)
lmhead_mma(const int* __restrict__ target) {
    extern __shared__ __align__(128) unsigned char dsm[];
    __shared__ float smax[4][MT], ssum[4][MT], stl[4][MT];

    const int tid = threadIdx.x, lane = tid & 31, warp = tid >> 5;
    const int wm = warp & 3, wn = warp >> 2;
    const uint32_t sbase = smem_u32(dsm);

    // producer mapping: 384 rows x 8 chunks(16B) = 3072 ids; 6 per thread
    int prow[6], pchk[6];
    #pragma unroll
    for (int j = 0; j < 6; j++) { const int id = tid + j * NTHREADS; prow[j] = id >> 3; pchk[j] = id & 7; }

    // ldmatrix base offsets
    const int l15 = lane & 15, lh = lane >> 4, lq = lane & 3, rq = lane >> 2;
    const uint32_t aBase = (uint32_t)(wm * 32 + l15) * ROWB + lh * 16;
    const uint32_t bBase = A_BYTES + (uint32_t)(wn * 64 + l15) * ROWB + lh * 16;

    float acc[2][8][4];
    #pragma unroll
    for (int mi = 0; mi < 2; mi++)
        #pragma unroll
        for (int nj = 0; nj < 8; nj++)
            #pragma unroll
            for (int q = 0; q < 4; q++) acc[mi][nj][q] = 0.f;

    for (int job = blockIdx.x; job < NJOBS; job += gridDim.x) {
        const int mb = job / NGRP, g = job - mb * NGRP;
        const int m0 = mb * MT;
        const int t0 = g * TPG;
        const int niter = TPG * KSTG;   // 320

        // per-job logsumexp state: 4 rows/lane
        float rmax[4], rsum[4], tlog[4];
        int tgtr[4];
        #pragma unroll
        for (int i = 0; i < 4; i++) { rmax[i] = -FLT_MAX; rsum[i] = 0.f; tlog[i] = 0.f; }
        #pragma unroll
        for (int mi = 0; mi < 2; mi++)
            #pragma unroll
            for (int h = 0; h < 2; h++)
                tgtr[mi * 2 + h] = target[m0 + wm * 32 + mi * 16 + h * 8 + rq];

        // pipeline prologue: stages 0..NST-2 (all within first tile of the job)
        #pragma unroll
        for (int s = 0; s < NST - 1; s++)
            fill_stage(sbase + s * STAGE_BYTES, m0, t0 * NTILE, s * KS, prow, pchk);

        for (int it = 0; it < niter; ++it) {
            CP_WAIT(NST - 2);
            __syncthreads();
            const uint32_t st = sbase + (it & (NST - 1)) * STAGE_BYTES;

            #pragma unroll
            for (int k2 = 0; k2 < 4; k2++) {
                uint32_t Af[2][4], Bf[4][4];
                #pragma unroll
                for (int mi = 0; mi < 2; mi++)
                    LDSM4(Af[mi][0], Af[mi][1], Af[mi][2], Af[mi][3],
                          st + aBase + mi * 16 * ROWB + k2 * 32);
                #pragma unroll
                for (int gg = 0; gg < 4; gg++)
                    LDSM4(Bf[gg][0], Bf[gg][1], Bf[gg][2], Bf[gg][3],
                          st + bBase + gg * 16 * ROWB + k2 * 32);
                #pragma unroll
                for (int mi = 0; mi < 2; mi++)
                    #pragma unroll
                    for (int gg = 0; gg < 4; gg++) {
                        MMA16816(acc[mi][2*gg],   Af[mi][0],Af[mi][1],Af[mi][2],Af[mi][3], Bf[gg][0], Bf[gg][2]);
                        MMA16816(acc[mi][2*gg+1], Af[mi][0],Af[mi][1],Af[mi][2],Af[mi][3], Bf[gg][1], Bf[gg][3]);
                    }
            }

            // prefetch stage it+NST-1
            const int pit = it + NST - 1;
            if (pit < niter) {
                fill_stage(sbase + (pit & (NST - 1)) * STAGE_BYTES, m0,
                           (t0 + (pit >> 6)) * NTILE, (pit & (KSTG - 1)) * KS, prow, pchk);
            } else {
                CP_COMMIT();   // keep group count in lockstep
            }

            // per-tile epilogue after last kstage of each tile
            if ((it & (KSTG - 1)) == KSTG - 1) {
                const int vcol0 = (t0 + (it >> 6)) * NTILE;
                #pragma unroll
                for (int mi = 0; mi < 2; mi++)
                    #pragma unroll
                    for (int h = 0; h < 2; h++) {
                        const int ri = mi * 2 + h;
                        float vmax = -FLT_MAX;
                        #pragma unroll
                        for (int nj = 0; nj < 8; nj++) {
                            vmax = fmaxf(vmax, acc[mi][nj][h * 2]);
                            vmax = fmaxf(vmax, acc[mi][nj][h * 2 + 1]);
                        }
                        const float nm = fmaxf(rmax[ri], vmax);
                        float s = 0.f;
                        #pragma unroll
                        for (int nj = 0; nj < 8; nj++) {
                            s += __expf(acc[mi][nj][h * 2]     - nm);
                            s += __expf(acc[mi][nj][h * 2 + 1] - nm);
                        }
                        rsum[ri] = rsum[ri] * __expf(rmax[ri] - nm) + s;
                        rmax[ri] = nm;
                        const int dt = tgtr[ri] - vcol0;
                        if (dt >= 0 && dt < NTILE) {
                            #pragma unroll
                            for (int nj = 0; nj < 8; nj++) {
                                const int c0 = wn * 64 + (nj >> 1) * 16 + (nj & 1) * 8 + lq * 2;
                                if (dt == c0)     tlog[ri] = acc[mi][nj][h * 2];
                                if (dt == c0 + 1) tlog[ri] = acc[mi][nj][h * 2 + 1];
                            }
                        }
                        #pragma unroll
                        for (int nj = 0; nj < 8; nj++) {
                            acc[mi][nj][h * 2] = 0.f; acc[mi][nj][h * 2 + 1] = 0.f;
                        }
                    }
            }
        }

        // merge lanes with same rows (xor 1, 2 over lq)
        #pragma unroll
        for (int ri = 0; ri < 4; ri++) {
            #pragma unroll
            for (int off = 1; off < 4; off <<= 1) {
                const float om = __shfl_xor_sync(0xFFFFFFFFu, rmax[ri], off);
                const float os = __shfl_xor_sync(0xFFFFFFFFu, rsum[ri], off);
                const float nm = fmaxf(rmax[ri], om);
                rsum[ri] = rsum[ri] * __expf(rmax[ri] - nm) + os * __expf(om - nm);
                rmax[ri] = nm;
                tlog[ri] += __shfl_xor_sync(0xFFFFFFFFu, tlog[ri], off);
            }
        }
        // cross-warp merge over the 4 wn columns
        if (lq == 0) {
            #pragma unroll
            for (int ri = 0; ri < 4; ri++) {
                const int row = wm * 32 + (ri >> 1) * 16 + (ri & 1) * 8 + rq;
                smax[wn][row] = rmax[ri];
                ssum[wn][row] = rsum[ri];
                stl[wn][row]  = tlog[ri];
            }
        }
        __syncthreads();
        if (tid < MT) {
            float M = smax[0][tid];
            #pragma unroll
            for (int w = 1; w < 4; w++) M = fmaxf(M, smax[w][tid]);
            float S = 0.f, T = 0.f;
            #pragma unroll
            for (int w = 0; w < 4; w++) { S += ssum[w][tid] * __expf(smax[w][tid] - M); T += stl[w][tid]; }
            g_pmax[g * N_TOK + m0 + tid] = M;
            g_psum[g * N_TOK + m0 + tid] = S;
            const int t = target[m0 + tid];
            if (t >= t0 * NTILE && t < (t0 + TPG) * NTILE)
                g_tlog[m0 + tid] = T;
        }
        __syncthreads();   // protect smax/ssum/stl before next job's merge
    }
}

// -------- combine splits per row, block-sum NLL --------
__global__ void reduce1_kernel(const int* __restrict__ target) {
    const int r = blockIdx.x * 128 + threadIdx.x;
    float M = -FLT_MAX;
    #pragma unroll
    for (int s = 0; s < NGRP; s++) M = fmaxf(M, g_pmax[s * N_TOK + r]);
    float S = 0.f;
    #pragma unroll
    for (int s = 0; s < NGRP; s++) S += g_psum[s * N_TOK + r] * __expf(g_pmax[s * N_TOK + r] - M);
    int t = target[r];
    int valid = (t != -100);
    float nll = valid ? (M + logf(S) - g_tlog[r]) : 0.f;

    __shared__ float sh[128];
    __shared__ int   sc[128];
    sh[threadIdx.x] = nll; sc[threadIdx.x] = valid;
    __syncthreads();
    for (int o = 64; o > 0; o >>= 1) {
        if (threadIdx.x < o) { sh[threadIdx.x] += sh[threadIdx.x + o]; sc[threadIdx.x] += sc[threadIdx.x + o]; }
        __syncthreads();
    }
    if (threadIdx.x == 0) { g_bnll[blockIdx.x] = sh[0]; g_bcnt[blockIdx.x] = sc[0]; }
}

__global__ void reduce2_kernel(float* __restrict__ out) {
    __shared__ float sh[64];
    __shared__ int   sc[64];
    int t = threadIdx.x;
    sh[t] = g_bnll[t]; sc[t] = g_bcnt[t];
    __syncthreads();
    for (int o = 32; o > 0; o >>= 1) {
        if (t < o) { sh[t] += sh[t + o]; sc[t] += sc[t + o]; }
        __syncthreads();
    }
    if (t == 0) {
        int c = sc[0] > 0 ? sc[0] : 1;
        out[0] = sh[0] / (float)c;
    }
}

extern "C" void kernel_launch(void* const* d_in, const int* in_sizes, int n_in,
                              void* d_out, int out_size) {
    const float* input  = (const float*)d_in[0];   // [8192,4096] f32
    const float* weight = (const float*)d_in[1];   // [32000,4096] f32
    const int* target   = (const int*)d_in[2];     // [8192] int32
    float* out = (float*)d_out;

    static int nsm = 0;
    if (!nsm) {
        cudaFuncSetAttribute(lmhead_mma, cudaFuncAttributeMaxDynamicSharedMemorySize, SMEM_DYN);
        cudaDeviceGetAttribute(&nsm, cudaDevAttrMultiProcessorCount, 0);
        if (nsm <= 0) nsm = 148;
    }

    cvt_kernel<<<4096, 256>>>(input,  (size_t)N_TOK * KDIM / 4, 0);
    cvt_kernel<<<8192, 256>>>(weight, (size_t)VDIM * KDIM / 4, 1);

    lmhead_mma<<<nsm, NTHREADS, SMEM_DYN>>>(target);

    reduce1_kernel<<<MBLK, 128>>>(target);
    reduce2_kernel<<<1, 64>>>(out);
}